// round 3
// baseline (speedup 1.0000x reference)
#include <cuda_runtime.h>
#include <cuda_bf16.h>

// Problem constants (fixed by the dataset)
#define NN      50000
#define FDIM    128
#define HEADS   4
#define HID     32
#define NGRAPH  64
#define OUTCH   10
#define NEG     0.2f
#define MAXE    800000
#define MAXTOT  (MAXE + NN)   // edges + self loops

// ---------------- device scratch (static, no allocation) ----------------
__device__ __align__(16) float    g_H[NN * FDIM];       // gemm output (pre-bias h)
__device__ __align__(16) float    g_P[NN * FDIM];       // ping buffer (agg/out)
__device__ __align__(16) float    g_Q[NN * FDIM];       // pong buffer
__device__ __align__(16) float    g_asrc[NN * HEADS];
__device__ __align__(16) float    g_adst[NN * HEADS];
__device__ __align__(16) unsigned g_maxe[NN * HEADS];   // encoded-float max
__device__ __align__(16) float    g_denom[NN * HEADS];  // sum, then reciprocal
__device__ __align__(16) float    g_ex[MAXTOT * HEADS]; // exp(e - m) per edge per head
__device__ __align__(16) float    g_pooled[NGRAPH * FDIM];

// monotone float<->uint encoding for atomicMax over signed floats
__device__ __forceinline__ unsigned enc_f(float x) {
    unsigned b = __float_as_uint(x);
    return (b & 0x80000000u) ? ~b : (b | 0x80000000u);
}
__device__ __forceinline__ float dec_f(unsigned u) {
    return (u & 0x80000000u) ? __uint_as_float(u & 0x7FFFFFFFu)
                             : __uint_as_float(~u);
}
__device__ __forceinline__ float lrelu(float e) { return e > 0.f ? e : NEG * e; }

__device__ __forceinline__ float* sel_buf(int sel) {
    return sel == 1 ? g_P : g_Q;
}
__device__ __forceinline__ const float* sel_x(const float* ext, int sel) {
    return sel == 0 ? ext : (sel == 1 ? g_P : g_Q);
}

// ---------------- GEMM: H = X(N,128) @ W(128,128), fp32 ----------------
// 128x128 block tile, K-chunks of 32, 256 threads, 8x8 microtile.
__global__ void __launch_bounds__(256) gemm128(const float* __restrict__ Xext,
                                               int xsel,
                                               const float* __restrict__ W) {
    __shared__ __align__(16) float Xs[128 * 33];   // [row][k] padded (conflict-free)
    __shared__ __align__(16) float Ws[32 * 128];   // [k][col]
    const float* X = sel_x(Xext, xsel);

    int row0 = blockIdx.x * 128;
    int tid  = threadIdx.x;
    int tx   = tid & 15;   // col tile 0..15
    int ty   = tid >> 4;   // row tile 0..15

    float acc[8][8];
#pragma unroll
    for (int i = 0; i < 8; i++)
#pragma unroll
        for (int j = 0; j < 8; j++) acc[i][j] = 0.f;

    const int c4 = tid & 7;    // float4 col within k-chunk (0..7)
    const int r  = tid >> 3;   // 0..31
    const int wc4 = tid & 31;  // float4 col for W (0..31)
    const int wk  = tid >> 5;  // 0..7

    for (int kc = 0; kc < 128; kc += 32) {
        // X tile: rows row0..row0+127, cols kc..kc+31 -> Xs[row][k]
#pragma unroll
        for (int i = 0; i < 4; i++) {
            int rr = r + 32 * i;
            int grow = row0 + rr;
            float4 v = make_float4(0.f, 0.f, 0.f, 0.f);
            if (grow < NN)
                v = reinterpret_cast<const float4*>(X)[grow * 32 + (kc >> 2) + c4];
            Xs[rr * 33 + c4 * 4 + 0] = v.x;
            Xs[rr * 33 + c4 * 4 + 1] = v.y;
            Xs[rr * 33 + c4 * 4 + 2] = v.z;
            Xs[rr * 33 + c4 * 4 + 3] = v.w;
        }
        // W tile: Ws[k][col]
#pragma unroll
        for (int i = 0; i < 4; i++) {
            int kk = wk + 8 * i;
            reinterpret_cast<float4*>(Ws)[kk * 32 + wc4] =
                reinterpret_cast<const float4*>(W)[(kc + kk) * 32 + wc4];
        }
        __syncthreads();

#pragma unroll 4
        for (int k = 0; k < 32; k++) {
            float a[8], b[8];
#pragma unroll
            for (int i = 0; i < 8; i++) a[i] = Xs[(ty * 8 + i) * 33 + k];
            float4 b0 = reinterpret_cast<float4*>(Ws)[k * 32 + tx * 2];
            float4 b1 = reinterpret_cast<float4*>(Ws)[k * 32 + tx * 2 + 1];
            b[0] = b0.x; b[1] = b0.y; b[2] = b0.z; b[3] = b0.w;
            b[4] = b1.x; b[5] = b1.y; b[6] = b1.z; b[7] = b1.w;
#pragma unroll
            for (int i = 0; i < 8; i++)
#pragma unroll
                for (int j = 0; j < 8; j++) acc[i][j] += a[i] * b[j];
        }
        __syncthreads();
    }

#pragma unroll
    for (int i = 0; i < 8; i++) {
        int grow = row0 + ty * 8 + i;
        if (grow < NN) {
            float4 o0 = make_float4(acc[i][0], acc[i][1], acc[i][2], acc[i][3]);
            float4 o1 = make_float4(acc[i][4], acc[i][5], acc[i][6], acc[i][7]);
            float4* dst = reinterpret_cast<float4*>(&g_H[grow * 128 + tx * 8]);
            dst[0] = o0;
            dst[1] = o1;
        }
    }
}

// ---------------- per-node attention scalars: warp per node ----------------
__global__ void attn_kernel(const float* __restrict__ a_s,
                            const float* __restrict__ a_d) {
    int gw   = (blockIdx.x * blockDim.x + threadIdx.x) >> 5;
    int lane = threadIdx.x & 31;
    if (gw >= NN) return;
    float ps[4], pd[4];
#pragma unroll
    for (int i = 0; i < 4; i++) {
        int f = i * 32 + lane;
        float v = g_H[gw * 128 + f];
        ps[i] = v * a_s[f];
        pd[i] = v * a_d[f];
    }
#pragma unroll
    for (int off = 16; off > 0; off >>= 1) {
#pragma unroll
        for (int i = 0; i < 4; i++) {
            ps[i] += __shfl_xor_sync(0xffffffffu, ps[i], off);
            pd[i] += __shfl_xor_sync(0xffffffffu, pd[i], off);
        }
    }
    if (lane == 0) {
        reinterpret_cast<float4*>(g_asrc)[gw] = make_float4(ps[0], ps[1], ps[2], ps[3]);
        reinterpret_cast<float4*>(g_adst)[gw] = make_float4(pd[0], pd[1], pd[2], pd[3]);
    }
}

// ---------------- clear agg buffer + max/denom ----------------
__global__ void init_bufs(int aggsel) {
    int i = blockIdx.x * blockDim.x + threadIdx.x;
    float* agg = sel_buf(aggsel);
    if (i < NN * FDIM) agg[i] = 0.f;
    if (i < NN * HEADS) {
        g_maxe[i]  = 0u;   // encodes below any real float
        g_denom[i] = 0.f;
    }
}

// ---------------- edge pass 1: segment max ----------------
__global__ void edge_max(const int* __restrict__ srcs,
                         const int* __restrict__ dsts, int E, int total) {
    int i = blockIdx.x * blockDim.x + threadIdx.x;
    if (i >= total) return;
    int s, d;
    if (i < E) { s = srcs[i]; d = dsts[i]; }
    else       { s = d = i - E; }
    float4 as = reinterpret_cast<const float4*>(g_asrc)[s];
    float4 ad = reinterpret_cast<const float4*>(g_adst)[d];
    atomicMax(&g_maxe[d * 4 + 0], enc_f(lrelu(as.x + ad.x)));
    atomicMax(&g_maxe[d * 4 + 1], enc_f(lrelu(as.y + ad.y)));
    atomicMax(&g_maxe[d * 4 + 2], enc_f(lrelu(as.z + ad.z)));
    atomicMax(&g_maxe[d * 4 + 3], enc_f(lrelu(as.w + ad.w)));
}

// ---------------- edge pass 2: exp + segment sum ----------------
__global__ void edge_sum(const int* __restrict__ srcs,
                         const int* __restrict__ dsts, int E, int total) {
    int i = blockIdx.x * blockDim.x + threadIdx.x;
    if (i >= total) return;
    int s, d;
    if (i < E) { s = srcs[i]; d = dsts[i]; }
    else       { s = d = i - E; }
    float4 as = reinterpret_cast<const float4*>(g_asrc)[s];
    float4 ad = reinterpret_cast<const float4*>(g_adst)[d];
    float e0 = lrelu(as.x + ad.x);
    float e1 = lrelu(as.y + ad.y);
    float e2 = lrelu(as.z + ad.z);
    float e3 = lrelu(as.w + ad.w);
    float x0 = __expf(e0 - dec_f(g_maxe[d * 4 + 0]));
    float x1 = __expf(e1 - dec_f(g_maxe[d * 4 + 1]));
    float x2 = __expf(e2 - dec_f(g_maxe[d * 4 + 2]));
    float x3 = __expf(e3 - dec_f(g_maxe[d * 4 + 3]));
    reinterpret_cast<float4*>(g_ex)[i] = make_float4(x0, x1, x2, x3);
    atomicAdd(&g_denom[d * 4 + 0], x0);
    atomicAdd(&g_denom[d * 4 + 1], x1);
    atomicAdd(&g_denom[d * 4 + 2], x2);
    atomicAdd(&g_denom[d * 4 + 3], x3);
}

// ---------------- reciprocal of denom (once per node-head) ----------------
__global__ void recip_denom() {
    int i = blockIdx.x * blockDim.x + threadIdx.x;
    if (i < NN * HEADS)
        g_denom[i] = 1.0f / (g_denom[i] + 1e-16f);
}

// ---------------- edge pass 3: weighted aggregate (warp per edge) ----------------
__global__ void edge_aggr(const int* __restrict__ srcs,
                          const int* __restrict__ dsts, int E, int total,
                          int aggsel) {
    int gw   = (blockIdx.x * blockDim.x + threadIdx.x) >> 5;
    int lane = threadIdx.x & 31;
    if (gw >= total) return;
    int s, d;
    if (gw < E) { s = srcs[gw]; d = dsts[gw]; }
    else        { s = d = gw - E; }
    float alpha = 0.f;
    if (lane < 4)
        alpha = g_ex[gw * 4 + lane] * g_denom[d * 4 + lane];
    // lane handles features [lane*4, lane*4+4) -> head = lane/8
    alpha = __shfl_sync(0xffffffffu, alpha, lane >> 3);
    float4 hv = reinterpret_cast<const float4*>(g_H)[s * 32 + lane];
    float* base = sel_buf(aggsel) + d * 128 + lane * 4;
    atomicAdd(base + 0, hv.x * alpha);
    atomicAdd(base + 1, hv.y * alpha);
    atomicAdd(base + 2, hv.z * alpha);
    atomicAdd(base + 3, hv.w * alpha);
}

// ---------------- bias + relu, in place on agg buffer ----------------
__global__ void finalize_relu(int aggsel, const float* __restrict__ b) {
    int i = blockIdx.x * blockDim.x + threadIdx.x;
    if (i >= NN * FDIM) return;
    float* agg = sel_buf(aggsel);
    float v = agg[i] + b[i & 127];
    agg[i] = v > 0.f ? v : 0.f;
}

// ---------------- mean pool per graph (batch is sorted int32) ----------------
__device__ __forceinline__ int lbound_i(const int* a, int n, int v) {
    int lo = 0, hi = n;
    while (lo < hi) {
        int mid = (lo + hi) >> 1;
        if (a[mid] < v) lo = mid + 1; else hi = mid;
    }
    return lo;
}

__global__ void pool_kernel(const int* __restrict__ batch, int sel) {
    __shared__ int se[2];
    __shared__ float s[128];
    int g = blockIdx.x;
    int t = threadIdx.x;
    if (t == 0) {
        se[0] = lbound_i(batch, NN, g);
        se[1] = lbound_i(batch, NN, g + 1);
    }
    __syncthreads();
    int start = se[0], end = se[1];
    const float* h = sel_buf(sel);
    int f = t & 127;
    float acc = 0.f;
    for (int n = start + (t >> 7); n < end; n += 2)
        acc += h[n * 128 + f];
    if (t < 128) s[t] = acc;
    __syncthreads();
    if (t >= 128) s[f] += acc;   // exactly one writer per f
    __syncthreads();
    if (t < 128)
        g_pooled[g * 128 + t] = s[t] / fmaxf((float)(end - start), 1.0f);
}

// ---------------- final FC: [64,128] @ [128,10] + b ----------------
__global__ void fc_kernel(const float* __restrict__ fcW,
                          const float* __restrict__ fcb,
                          float* __restrict__ out) {
    int t = threadIdx.x;
    if (t >= NGRAPH * OUTCH) return;
    int g = t / OUTCH, o = t % OUTCH;
    float acc = fcb[o];
#pragma unroll 8
    for (int k = 0; k < 128; k++)
        acc += g_pooled[g * 128 + k] * fcW[k * OUTCH + o];
    out[t] = acc;
}

// ---------------- driver ----------------
static void run_layer(const float* x_ext, int xsel, int aggsel,
                      const float* W, const float* a_s, const float* a_d,
                      const float* b, const int* srcs, const int* dsts,
                      int E, int total) {
    gemm128<<<(NN + 127) / 128, 256>>>(x_ext, xsel, W);
    attn_kernel<<<(NN + 7) / 8, 256>>>(a_s, a_d);
    init_bufs<<<(NN * FDIM + 255) / 256, 256>>>(aggsel);
    edge_max<<<(total + 255) / 256, 256>>>(srcs, dsts, E, total);
    edge_sum<<<(total + 255) / 256, 256>>>(srcs, dsts, E, total);
    recip_denom<<<(NN * HEADS + 255) / 256, 256>>>();
    edge_aggr<<<(total + 7) / 8, 256>>>(srcs, dsts, E, total, aggsel);
    finalize_relu<<<(NN * FDIM + 255) / 256, 256>>>(aggsel, b);
}

extern "C" void kernel_launch(void* const* d_in, const int* in_sizes, int n_in,
                              void* d_out, int out_size) {
    const float* x     = (const float*)d_in[0];
    const int*   ei    = (const int*)d_in[1];    // int32 (JAX x64 disabled)
    const int*   batch = (const int*)d_in[2];
    const float* W1  = (const float*)d_in[3];
    const float* a1s = (const float*)d_in[4];
    const float* a1d = (const float*)d_in[5];
    const float* b1  = (const float*)d_in[6];
    const float* W2  = (const float*)d_in[7];
    const float* a2s = (const float*)d_in[8];
    const float* a2d = (const float*)d_in[9];
    const float* b2  = (const float*)d_in[10];
    const float* W3  = (const float*)d_in[11];
    const float* a3s = (const float*)d_in[12];
    const float* a3d = (const float*)d_in[13];
    const float* b3  = (const float*)d_in[14];
    const float* fcW = (const float*)d_in[15];
    const float* fcb = (const float*)d_in[16];

    int E = in_sizes[1] / 2;
    int total = E + NN;
    const int* srcs = ei;
    const int* dsts = ei + E;

    // layer 1: x -> P,  layer 2: P -> Q,  layer 3: Q -> P
    run_layer(x,       0, 1, W1, a1s, a1d, b1, srcs, dsts, E, total);
    run_layer(nullptr, 1, 2, W2, a2s, a2d, b2, srcs, dsts, E, total);
    run_layer(nullptr, 2, 1, W3, a3s, a3d, b3, srcs, dsts, E, total);

    pool_kernel<<<NGRAPH, 256>>>(batch, 1);
    fc_kernel<<<1, NGRAPH * OUTCH>>>(fcW, fcb, (float*)d_out);
}

// round 4
// speedup vs baseline: 2.5612x; 2.5612x over previous
#include <cuda_runtime.h>
#include <cuda_bf16.h>

// Problem constants (fixed by the dataset)
#define NN      50000
#define FDIM    128
#define HEADS   4
#define NGRAPH  64
#define OUTCH   10
#define NEG     0.2f
#define MAXE    800000
#define MAXTOT  (MAXE + NN)   // edges + self loops

// ---------------- device scratch (static, no allocation) ----------------
__device__ __align__(16) float g_H[NN * FDIM];     // gemm output (pre-bias h)
__device__ __align__(16) float g_P[NN * FDIM];     // ping buffer
__device__ __align__(16) float g_Q[NN * FDIM];     // pong buffer
__device__ __align__(16) float g_asrc[NN * HEADS];
__device__ __align__(16) float g_adst[NN * HEADS];
__device__ __align__(16) float g_pooled[NGRAPH * FDIM];
// CSR by destination (built once per launch; graph static across layers)
__device__ int g_deg[NN];
__device__ int g_off[NN + 1];
__device__ int g_cursor[NN];
__device__ int g_csr_src[MAXTOT];

__device__ __forceinline__ float lrelu(float e) { return e > 0.f ? e : NEG * e; }

__device__ __forceinline__ float* sel_buf(int sel) {
    return sel == 1 ? g_P : g_Q;
}
__device__ __forceinline__ const float* sel_x(const float* ext, int sel) {
    return sel == 0 ? ext : (sel == 1 ? g_P : g_Q);
}

// ================= CSR build (once per launch) =================
__global__ void init_deg() {
    int i = blockIdx.x * blockDim.x + threadIdx.x;
    if (i < NN) g_deg[i] = 1;          // self loop
}
__global__ void count_deg(const int* __restrict__ dsts, int E) {
    int i = blockIdx.x * blockDim.x + threadIdx.x;
    if (i < E) atomicAdd(&g_deg[dsts[i]], 1);
}
// one block, 1024 threads: chunked exclusive scan of g_deg -> g_off, g_cursor
__global__ void scan_deg() {
    __shared__ int part[1024];
    const int CH = (NN + 1023) / 1024;   // 49
    int t = threadIdx.x;
    int base = t * CH;
    int s = 0;
    for (int k = 0; k < CH; k++) {
        int idx = base + k;
        if (idx < NN) s += g_deg[idx];
    }
    part[t] = s;
    __syncthreads();
    for (int off = 1; off < 1024; off <<= 1) {
        int v = (t >= off) ? part[t - off] : 0;
        __syncthreads();
        part[t] += v;
        __syncthreads();
    }
    int run = part[t] - s;     // exclusive start of this chunk
    for (int k = 0; k < CH; k++) {
        int idx = base + k;
        if (idx < NN) {
            g_off[idx]    = run;
            g_cursor[idx] = run;
            run += g_deg[idx];
        }
    }
    if (t == 0) g_off[NN] = part[1023];
}
__global__ void scatter_edges(const int* __restrict__ srcs,
                              const int* __restrict__ dsts, int E, int total) {
    int i = blockIdx.x * blockDim.x + threadIdx.x;
    if (i >= total) return;
    int s, d;
    if (i < E) { s = srcs[i]; d = dsts[i]; }
    else       { s = d = i - E; }
    int pos = atomicAdd(&g_cursor[d], 1);
    g_csr_src[pos] = s;
}

// ======= GEMM: H = X(N,128) @ W(128,128), fp32; fused attn-scalar epilogue =======
// 128x128 block tile, K-chunks of 32, 256 threads, 8x8 microtile.
__global__ void __launch_bounds__(256) gemm128(const float* __restrict__ Xext,
                                               int xsel,
                                               const float* __restrict__ W,
                                               const float* __restrict__ a_s,
                                               const float* __restrict__ a_d) {
    __shared__ __align__(16) float Xs[128 * 33];   // [row][k] padded
    __shared__ __align__(16) float Ws[32 * 128];   // [k][col]
    __shared__ float as_s[128], ad_s[128];
    const float* X = sel_x(Xext, xsel);

    int row0 = blockIdx.x * 128;
    int tid  = threadIdx.x;
    int tx   = tid & 15;   // col tile 0..15
    int ty   = tid >> 4;   // row tile 0..15

    if (tid < 128) { as_s[tid] = a_s[tid]; ad_s[tid] = a_d[tid]; }

    float acc[8][8];
#pragma unroll
    for (int i = 0; i < 8; i++)
#pragma unroll
        for (int j = 0; j < 8; j++) acc[i][j] = 0.f;

    const int c4 = tid & 7;    // float4 col within k-chunk (0..7)
    const int r  = tid >> 3;   // 0..31
    const int wc4 = tid & 31;  // float4 col for W (0..31)
    const int wk  = tid >> 5;  // 0..7

    for (int kc = 0; kc < 128; kc += 32) {
#pragma unroll
        for (int i = 0; i < 4; i++) {
            int rr = r + 32 * i;
            int grow = row0 + rr;
            float4 v = make_float4(0.f, 0.f, 0.f, 0.f);
            if (grow < NN)
                v = reinterpret_cast<const float4*>(X)[grow * 32 + (kc >> 2) + c4];
            Xs[rr * 33 + c4 * 4 + 0] = v.x;
            Xs[rr * 33 + c4 * 4 + 1] = v.y;
            Xs[rr * 33 + c4 * 4 + 2] = v.z;
            Xs[rr * 33 + c4 * 4 + 3] = v.w;
        }
#pragma unroll
        for (int i = 0; i < 4; i++) {
            int kk = wk + 8 * i;
            reinterpret_cast<float4*>(Ws)[kk * 32 + wc4] =
                reinterpret_cast<const float4*>(W)[(kc + kk) * 32 + wc4];
        }
        __syncthreads();

#pragma unroll 4
        for (int k = 0; k < 32; k++) {
            float a[8], b[8];
#pragma unroll
            for (int i = 0; i < 8; i++) a[i] = Xs[(ty * 8 + i) * 33 + k];
            float4 b0 = reinterpret_cast<float4*>(Ws)[k * 32 + tx * 2];
            float4 b1 = reinterpret_cast<float4*>(Ws)[k * 32 + tx * 2 + 1];
            b[0] = b0.x; b[1] = b0.y; b[2] = b0.z; b[3] = b0.w;
            b[4] = b1.x; b[5] = b1.y; b[6] = b1.z; b[7] = b1.w;
#pragma unroll
            for (int i = 0; i < 8; i++)
#pragma unroll
                for (int j = 0; j < 8; j++) acc[i][j] += a[i] * b[j];
        }
        __syncthreads();
    }

#pragma unroll
    for (int i = 0; i < 8; i++) {
        int grow = row0 + ty * 8 + i;
        if (grow < NN) {
            float4 o0 = make_float4(acc[i][0], acc[i][1], acc[i][2], acc[i][3]);
            float4 o1 = make_float4(acc[i][4], acc[i][5], acc[i][6], acc[i][7]);
            float4* dst = reinterpret_cast<float4*>(&g_H[grow * 128 + tx * 8]);
            dst[0] = o0;
            dst[1] = o1;
        }
        // fused attention scalars: head = tx>>2; reduce over tx&3 (lane bits 0-1)
        float ps = 0.f, pd = 0.f;
#pragma unroll
        for (int j = 0; j < 8; j++) {
            int col = tx * 8 + j;
            ps += acc[i][j] * as_s[col];
            pd += acc[i][j] * ad_s[col];
        }
        ps += __shfl_xor_sync(0xffffffffu, ps, 1);
        ps += __shfl_xor_sync(0xffffffffu, ps, 2);
        pd += __shfl_xor_sync(0xffffffffu, pd, 1);
        pd += __shfl_xor_sync(0xffffffffu, pd, 2);
        if ((tx & 3) == 0 && grow < NN) {
            g_asrc[grow * 4 + (tx >> 2)] = ps;
            g_adst[grow * 4 + (tx >> 2)] = pd;
        }
    }
}

// ======= fused softmax + aggregate: one warp per destination node =======
__global__ void __launch_bounds__(256) fused_edge(int aggsel,
                                                  const float* __restrict__ b) {
    int gw   = (blockIdx.x * blockDim.x + threadIdx.x) >> 5;
    int lane = threadIdx.x & 31;
    if (gw >= NN) return;
    const int d   = gw;
    const int beg = g_off[d];
    const int end = g_off[d + 1];   // >= beg+1 (self loop)

    float4 ad4 = reinterpret_cast<const float4*>(g_adst)[d];

    // pass 1: per-head max (lane-strided)
    float m0 = -3.4e38f, m1 = -3.4e38f, m2 = -3.4e38f, m3 = -3.4e38f;
    for (int i = beg + lane; i < end; i += 32) {
        int s = g_csr_src[i];
        float4 as = reinterpret_cast<const float4*>(g_asrc)[s];
        m0 = fmaxf(m0, lrelu(as.x + ad4.x));
        m1 = fmaxf(m1, lrelu(as.y + ad4.y));
        m2 = fmaxf(m2, lrelu(as.z + ad4.z));
        m3 = fmaxf(m3, lrelu(as.w + ad4.w));
    }
#pragma unroll
    for (int off = 16; off > 0; off >>= 1) {
        m0 = fmaxf(m0, __shfl_xor_sync(0xffffffffu, m0, off));
        m1 = fmaxf(m1, __shfl_xor_sync(0xffffffffu, m1, off));
        m2 = fmaxf(m2, __shfl_xor_sync(0xffffffffu, m2, off));
        m3 = fmaxf(m3, __shfl_xor_sync(0xffffffffu, m3, off));
    }

    // pass 2: per-head sum of exp(e-m)
    float s0 = 0.f, s1 = 0.f, s2 = 0.f, s3 = 0.f;
    for (int i = beg + lane; i < end; i += 32) {
        int s = g_csr_src[i];
        float4 as = reinterpret_cast<const float4*>(g_asrc)[s];
        s0 += __expf(lrelu(as.x + ad4.x) - m0);
        s1 += __expf(lrelu(as.y + ad4.y) - m1);
        s2 += __expf(lrelu(as.z + ad4.z) - m2);
        s3 += __expf(lrelu(as.w + ad4.w) - m3);
    }
#pragma unroll
    for (int off = 16; off > 0; off >>= 1) {
        s0 += __shfl_xor_sync(0xffffffffu, s0, off);
        s1 += __shfl_xor_sync(0xffffffffu, s1, off);
        s2 += __shfl_xor_sync(0xffffffffu, s2, off);
        s3 += __shfl_xor_sync(0xffffffffu, s3, off);
    }
    float r0 = 1.f / (s0 + 1e-16f);
    float r1 = 1.f / (s1 + 1e-16f);
    float r2 = 1.f / (s2 + 1e-16f);
    float r3 = 1.f / (s3 + 1e-16f);

    // per-lane constants for the alpha computation (lanes 0-3 compute head=lane)
    float ml   = (lane & 2) ? ((lane & 1) ? m3 : m2) : ((lane & 1) ? m1 : m0);
    float rl   = (lane & 2) ? ((lane & 1) ? r3 : r2) : ((lane & 1) ? r1 : r0);
    float adl  = (lane & 2) ? ((lane & 1) ? ad4.w : ad4.z)
                            : ((lane & 1) ? ad4.y : ad4.x);
    const int h = lane >> 3;   // head owning this lane's 4 features

    // pass 3: whole-warp per edge, accumulate in registers, single store
    float4 acc = make_float4(0.f, 0.f, 0.f, 0.f);
    for (int i = beg; i < end; i++) {
        int s = g_csr_src[i];                         // broadcast load
        float a = 0.f;
        if (lane < 4)
            a = __expf(lrelu(g_asrc[s * 4 + lane] + adl) - ml) * rl;
        a = __shfl_sync(0xffffffffu, a, h);
        float4 hv = reinterpret_cast<const float4*>(g_H)[s * 32 + lane];
        acc.x += a * hv.x;
        acc.y += a * hv.y;
        acc.z += a * hv.z;
        acc.w += a * hv.w;
    }
    float4 bb = reinterpret_cast<const float4*>(b)[lane];
    float4 o;
    o.x = fmaxf(acc.x + bb.x, 0.f);
    o.y = fmaxf(acc.y + bb.y, 0.f);
    o.z = fmaxf(acc.z + bb.z, 0.f);
    o.w = fmaxf(acc.w + bb.w, 0.f);
    reinterpret_cast<float4*>(sel_buf(aggsel))[d * 32 + lane] = o;
}

// ---------------- mean pool per graph (batch is sorted int32) ----------------
__device__ __forceinline__ int lbound_i(const int* a, int n, int v) {
    int lo = 0, hi = n;
    while (lo < hi) {
        int mid = (lo + hi) >> 1;
        if (a[mid] < v) lo = mid + 1; else hi = mid;
    }
    return lo;
}

__global__ void pool_kernel(const int* __restrict__ batch, int sel) {
    __shared__ int se[2];
    __shared__ float s[128];
    int g = blockIdx.x;
    int t = threadIdx.x;
    if (t == 0) {
        se[0] = lbound_i(batch, NN, g);
        se[1] = lbound_i(batch, NN, g + 1);
    }
    __syncthreads();
    int start = se[0], end = se[1];
    const float* h = sel_buf(sel);
    int f = t & 127;
    float acc = 0.f;
    for (int n = start + (t >> 7); n < end; n += 2)
        acc += h[n * 128 + f];
    if (t < 128) s[t] = acc;
    __syncthreads();
    if (t >= 128) s[f] += acc;   // exactly one writer per f
    __syncthreads();
    if (t < 128)
        g_pooled[g * 128 + t] = s[t] / fmaxf((float)(end - start), 1.0f);
}

// ---------------- final FC: [64,128] @ [128,10] + b ----------------
__global__ void fc_kernel(const float* __restrict__ fcW,
                          const float* __restrict__ fcb,
                          float* __restrict__ out) {
    int t = threadIdx.x;
    if (t >= NGRAPH * OUTCH) return;
    int g = t / OUTCH, o = t % OUTCH;
    float acc = fcb[o];
#pragma unroll 8
    for (int k = 0; k < 128; k++)
        acc += g_pooled[g * 128 + k] * fcW[k * OUTCH + o];
    out[t] = acc;
}

// ---------------- driver ----------------
static void run_layer(const float* x_ext, int xsel, int aggsel,
                      const float* W, const float* a_s, const float* a_d,
                      const float* b) {
    gemm128<<<(NN + 127) / 128, 256>>>(x_ext, xsel, W, a_s, a_d);
    fused_edge<<<(NN + 7) / 8, 256>>>(aggsel, b);
}

extern "C" void kernel_launch(void* const* d_in, const int* in_sizes, int n_in,
                              void* d_out, int out_size) {
    const float* x     = (const float*)d_in[0];
    const int*   ei    = (const int*)d_in[1];    // int32 (JAX x64 disabled)
    const int*   batch = (const int*)d_in[2];
    const float* W1  = (const float*)d_in[3];
    const float* a1s = (const float*)d_in[4];
    const float* a1d = (const float*)d_in[5];
    const float* b1  = (const float*)d_in[6];
    const float* W2  = (const float*)d_in[7];
    const float* a2s = (const float*)d_in[8];
    const float* a2d = (const float*)d_in[9];
    const float* b2  = (const float*)d_in[10];
    const float* W3  = (const float*)d_in[11];
    const float* a3s = (const float*)d_in[12];
    const float* a3d = (const float*)d_in[13];
    const float* b3  = (const float*)d_in[14];
    const float* fcW = (const float*)d_in[15];
    const float* fcb = (const float*)d_in[16];

    int E = in_sizes[1] / 2;
    int total = E + NN;
    const int* srcs = ei;
    const int* dsts = ei + E;

    // CSR build (graph static across layers)
    init_deg<<<(NN + 255) / 256, 256>>>();
    count_deg<<<(E + 255) / 256, 256>>>(dsts, E);
    scan_deg<<<1, 1024>>>();
    scatter_edges<<<(total + 255) / 256, 256>>>(srcs, dsts, E, total);

    // layer 1: x -> P,  layer 2: P -> Q,  layer 3: Q -> P
    run_layer(x,       0, 1, W1, a1s, a1d, b1);
    run_layer(nullptr, 1, 2, W2, a2s, a2d, b2);
    run_layer(nullptr, 2, 1, W3, a3s, a3d, b3);

    pool_kernel<<<NGRAPH, 256>>>(batch, 1);
    fc_kernel<<<1, NGRAPH * OUTCH>>>(fcW, fcb, (float*)d_out);
}

// round 6
// speedup vs baseline: 2.9454x; 1.1500x over previous
#include <cuda_runtime.h>
#include <cuda_bf16.h>
#include <cuda_fp16.h>
#include <cstdint>

// Problem constants (fixed by the dataset)
#define NN      50000
#define FDIM    128
#define HEADS   4
#define NGRAPH  64
#define OUTCH   10
#define NEG     0.2f
#define MAXE    800000
#define MAXTOT  (MAXE + NN)   // edges + self loops

// ---------------- device scratch (static, no allocation) ----------------
__device__ __align__(16) __half g_Hh[NN * FDIM];   // gemm output (pre-bias h), fp16
__device__ __align__(16) float  g_P[NN * FDIM];    // ping buffer
__device__ __align__(16) float  g_Q[NN * FDIM];    // pong buffer
__device__ __align__(16) float  g_asrc[NN * HEADS];
__device__ __align__(16) float  g_adst[NN * HEADS];
__device__ __align__(16) float  g_ex[MAXTOT * HEADS]; // exp(e) per edge per head
__device__ __align__(16) float  g_pooled[NGRAPH * FDIM];
// CSR by destination (built once per launch; graph static across layers)
__device__ int g_deg[NN];
__device__ int g_off[NN + 1];
__device__ int g_cursor[NN];
__device__ int g_csr_src[MAXTOT];

__device__ __forceinline__ float lrelu(float e) { return e > 0.f ? e : NEG * e; }

__device__ __forceinline__ float* sel_buf(int sel) {
    return sel == 1 ? g_P : g_Q;
}
__device__ __forceinline__ const float* sel_x(const float* ext, int sel) {
    return sel == 0 ? ext : (sel == 1 ? g_P : g_Q);
}

// ================= CSR build (once per launch) =================
__global__ void init_deg() {
    int i = blockIdx.x * blockDim.x + threadIdx.x;
    if (i < NN) g_deg[i] = 1;          // self loop
}
__global__ void count_deg(const int* __restrict__ dsts, int E) {
    int i = blockIdx.x * blockDim.x + threadIdx.x;
    if (i < E) atomicAdd(&g_deg[dsts[i]], 1);
}
// one block, 1024 threads: chunked exclusive scan of g_deg -> g_off, g_cursor
__global__ void scan_deg() {
    __shared__ int part[1024];
    const int CH = (NN + 1023) / 1024;   // 49
    int t = threadIdx.x;
    int base = t * CH;
    int s = 0;
    for (int k = 0; k < CH; k++) {
        int idx = base + k;
        if (idx < NN) s += g_deg[idx];
    }
    part[t] = s;
    __syncthreads();
    for (int off = 1; off < 1024; off <<= 1) {
        int v = (t >= off) ? part[t - off] : 0;
        __syncthreads();
        part[t] += v;
        __syncthreads();
    }
    int run = part[t] - s;     // exclusive start of this chunk
    for (int k = 0; k < CH; k++) {
        int idx = base + k;
        if (idx < NN) {
            g_off[idx]    = run;
            g_cursor[idx] = run;
            run += g_deg[idx];
        }
    }
    if (t == 0) g_off[NN] = part[1023];
}
__global__ void scatter_edges(const int* __restrict__ srcs,
                              const int* __restrict__ dsts, int E, int total) {
    int i = blockIdx.x * blockDim.x + threadIdx.x;
    if (i >= total) return;
    int s, d;
    if (i < E) { s = srcs[i]; d = dsts[i]; }
    else       { s = d = i - E; }
    int pos = atomicAdd(&g_cursor[d], 1);
    g_csr_src[pos] = s;
}

// ======= GEMM: H = X(N,128) @ W(128,128), fp32; fused attn-scalar epilogue =======
// 128x128 block tile, K-chunks of 32, 256 threads, 8x8 microtile.
__global__ void __launch_bounds__(256) gemm128(const float* __restrict__ Xext,
                                               int xsel,
                                               const float* __restrict__ W,
                                               const float* __restrict__ a_s,
                                               const float* __restrict__ a_d) {
    __shared__ __align__(16) float Xs[128 * 33];   // [row][k] padded
    __shared__ __align__(16) float Ws[32 * 128];   // [k][col]
    __shared__ float as_s[128], ad_s[128];
    const float* X = sel_x(Xext, xsel);

    int row0 = blockIdx.x * 128;
    int tid  = threadIdx.x;
    int tx   = tid & 15;   // col tile 0..15
    int ty   = tid >> 4;   // row tile 0..15

    if (tid < 128) { as_s[tid] = a_s[tid]; ad_s[tid] = a_d[tid]; }

    float acc[8][8];
#pragma unroll
    for (int i = 0; i < 8; i++)
#pragma unroll
        for (int j = 0; j < 8; j++) acc[i][j] = 0.f;

    const int c4 = tid & 7;    // float4 col within k-chunk (0..7)
    const int r  = tid >> 3;   // 0..31
    const int wc4 = tid & 31;  // float4 col for W (0..31)
    const int wk  = tid >> 5;  // 0..7

    for (int kc = 0; kc < 128; kc += 32) {
#pragma unroll
        for (int i = 0; i < 4; i++) {
            int rr = r + 32 * i;
            int grow = row0 + rr;
            float4 v = make_float4(0.f, 0.f, 0.f, 0.f);
            if (grow < NN)
                v = reinterpret_cast<const float4*>(X)[grow * 32 + (kc >> 2) + c4];
            Xs[rr * 33 + c4 * 4 + 0] = v.x;
            Xs[rr * 33 + c4 * 4 + 1] = v.y;
            Xs[rr * 33 + c4 * 4 + 2] = v.z;
            Xs[rr * 33 + c4 * 4 + 3] = v.w;
        }
#pragma unroll
        for (int i = 0; i < 4; i++) {
            int kk = wk + 8 * i;
            reinterpret_cast<float4*>(Ws)[kk * 32 + wc4] =
                reinterpret_cast<const float4*>(W)[(kc + kk) * 32 + wc4];
        }
        __syncthreads();

#pragma unroll 4
        for (int k = 0; k < 32; k++) {
            float a[8], b[8];
#pragma unroll
            for (int i = 0; i < 8; i++) a[i] = Xs[(ty * 8 + i) * 33 + k];
            float4 b0 = reinterpret_cast<float4*>(Ws)[k * 32 + tx * 2];
            float4 b1 = reinterpret_cast<float4*>(Ws)[k * 32 + tx * 2 + 1];
            b[0] = b0.x; b[1] = b0.y; b[2] = b0.z; b[3] = b0.w;
            b[4] = b1.x; b[5] = b1.y; b[6] = b1.z; b[7] = b1.w;
#pragma unroll
            for (int i = 0; i < 8; i++)
#pragma unroll
                for (int j = 0; j < 8; j++) acc[i][j] += a[i] * b[j];
        }
        __syncthreads();
    }

#pragma unroll
    for (int i = 0; i < 8; i++) {
        int grow = row0 + ty * 8 + i;
        if (grow < NN) {
            // store h as fp16 (consumed only by the edge-aggregate gather)
            __half2 hb[4];
#pragma unroll
            for (int j = 0; j < 4; j++)
                hb[j] = __floats2half2_rn(acc[i][2 * j], acc[i][2 * j + 1]);
            *reinterpret_cast<uint4*>(&g_Hh[grow * 128 + tx * 8]) =
                *reinterpret_cast<uint4*>(hb);
        }
        // fused attention scalars: head = tx>>2; reduce over tx&3 (lane bits 0-1)
        float ps = 0.f, pd = 0.f;
#pragma unroll
        for (int j = 0; j < 8; j++) {
            int col = tx * 8 + j;
            ps += acc[i][j] * as_s[col];
            pd += acc[i][j] * ad_s[col];
        }
        ps += __shfl_xor_sync(0xffffffffu, ps, 1);
        ps += __shfl_xor_sync(0xffffffffu, ps, 2);
        pd += __shfl_xor_sync(0xffffffffu, pd, 1);
        pd += __shfl_xor_sync(0xffffffffu, pd, 2);
        if ((tx & 3) == 0 && grow < NN) {
            g_asrc[grow * 4 + (tx >> 2)] = ps;
            g_adst[grow * 4 + (tx >> 2)] = pd;
        }
    }
}

// ======= fused softmax + aggregate: one warp per destination node =======
// No max pass: softmax(e) == softmax(e - m); e is O(+-5) so exp is safe
// (clamped at 30 as a guard). exp(e) cached per edge in g_ex.
__global__ void __launch_bounds__(256) fused_edge(int aggsel,
                                                  const float* __restrict__ b) {
    int gw   = (blockIdx.x * blockDim.x + threadIdx.x) >> 5;
    int lane = threadIdx.x & 31;
    if (gw >= NN) return;
    const int d   = gw;
    const int beg = g_off[d];
    const int end = g_off[d + 1];   // >= beg+1 (self loop)

    float4 ad4 = reinterpret_cast<const float4*>(g_adst)[d];

    // pass 1: exp(e) per edge (cached) + per-head denominator
    float s0 = 0.f, s1 = 0.f, s2 = 0.f, s3 = 0.f;
    for (int i = beg + lane; i < end; i += 32) {
        int s = g_csr_src[i];
        float4 as = reinterpret_cast<const float4*>(g_asrc)[s];
        float x0 = __expf(fminf(lrelu(as.x + ad4.x), 30.f));
        float x1 = __expf(fminf(lrelu(as.y + ad4.y), 30.f));
        float x2 = __expf(fminf(lrelu(as.z + ad4.z), 30.f));
        float x3 = __expf(fminf(lrelu(as.w + ad4.w), 30.f));
        reinterpret_cast<float4*>(g_ex)[i] = make_float4(x0, x1, x2, x3);
        s0 += x0; s1 += x1; s2 += x2; s3 += x3;
    }
#pragma unroll
    for (int off = 16; off > 0; off >>= 1) {
        s0 += __shfl_xor_sync(0xffffffffu, s0, off);
        s1 += __shfl_xor_sync(0xffffffffu, s1, off);
        s2 += __shfl_xor_sync(0xffffffffu, s2, off);
        s3 += __shfl_xor_sync(0xffffffffu, s3, off);
    }
    float r0 = 1.f / (s0 + 1e-16f);
    float r1 = 1.f / (s1 + 1e-16f);
    float r2 = 1.f / (s2 + 1e-16f);
    float r3 = 1.f / (s3 + 1e-16f);

    __threadfence_block();   // make this warp's g_ex stores visible to all lanes
    __syncwarp();

    // lanes 0-3 hold reciprocal denominator for head = lane
    float rl = (lane & 2) ? ((lane & 1) ? r3 : r2) : ((lane & 1) ? r1 : r0);
    const int h = lane >> 3;   // head owning this lane's 4 features

    // pass 2: whole-warp per edge, fp16 h gather, accumulate fp32, single store
    float4 acc = make_float4(0.f, 0.f, 0.f, 0.f);
    for (int i = beg; i < end; i++) {
        int s = g_csr_src[i];                 // broadcast load
        float a = 0.f;
        if (lane < 4)
            a = g_ex[i * 4 + lane] * rl;      // one 16B line, broadcast
        a = __shfl_sync(0xffffffffu, a, h);
        uint2 hv = reinterpret_cast<const uint2*>(g_Hh)[s * 32 + lane]; // 4 halfs
        float2 f01 = __half22float2(*reinterpret_cast<__half2*>(&hv.x));
        float2 f23 = __half22float2(*reinterpret_cast<__half2*>(&hv.y));
        acc.x += a * f01.x;
        acc.y += a * f01.y;
        acc.z += a * f23.x;
        acc.w += a * f23.y;
    }
    float4 bb = reinterpret_cast<const float4*>(b)[lane];
    float4 o;
    o.x = fmaxf(acc.x + bb.x, 0.f);
    o.y = fmaxf(acc.y + bb.y, 0.f);
    o.z = fmaxf(acc.z + bb.z, 0.f);
    o.w = fmaxf(acc.w + bb.w, 0.f);
    reinterpret_cast<float4*>(sel_buf(aggsel))[d * 32 + lane] = o;
}

// ---------------- mean pool per graph (batch is sorted int32) ----------------
__device__ __forceinline__ int lbound_i(const int* a, int n, int v) {
    int lo = 0, hi = n;
    while (lo < hi) {
        int mid = (lo + hi) >> 1;
        if (a[mid] < v) lo = mid + 1; else hi = mid;
    }
    return lo;
}

__global__ void pool_kernel(const int* __restrict__ batch, int sel) {
    __shared__ int se[2];
    __shared__ float s[128];
    int g = blockIdx.x;
    int t = threadIdx.x;
    if (t == 0) {
        se[0] = lbound_i(batch, NN, g);
        se[1] = lbound_i(batch, NN, g + 1);
    }
    __syncthreads();
    int start = se[0], end = se[1];
    const float* h = sel_buf(sel);
    int f = t & 127;
    float acc = 0.f;
    for (int n = start + (t >> 7); n < end; n += 2)
        acc += h[n * 128 + f];
    if (t < 128) s[t] = acc;
    __syncthreads();
    if (t >= 128) s[f] += acc;   // exactly one writer per f
    __syncthreads();
    if (t < 128)
        g_pooled[g * 128 + t] = s[t] / fmaxf((float)(end - start), 1.0f);
}

// ---------------- final FC: [64,128] @ [128,10] + b ----------------
__global__ void fc_kernel(const float* __restrict__ fcW,
                          const float* __restrict__ fcb,
                          float* __restrict__ out) {
    int t = threadIdx.x;
    if (t >= NGRAPH * OUTCH) return;
    int g = t / OUTCH, o = t % OUTCH;
    float acc = fcb[o];
#pragma unroll 8
    for (int k = 0; k < 128; k++)
        acc += g_pooled[g * 128 + k] * fcW[k * OUTCH + o];
    out[t] = acc;
}

// ---------------- driver ----------------
static void run_layer(const float* x_ext, int xsel, int aggsel,
                      const float* W, const float* a_s, const float* a_d,
                      const float* b) {
    gemm128<<<(NN + 127) / 128, 256>>>(x_ext, xsel, W, a_s, a_d);
    fused_edge<<<(NN + 7) / 8, 256>>>(aggsel, b);
}

extern "C" void kernel_launch(void* const* d_in, const int* in_sizes, int n_in,
                              void* d_out, int out_size) {
    const float* x     = (const float*)d_in[0];
    const int*   ei    = (const int*)d_in[1];    // int32 (JAX x64 disabled)
    const int*   batch = (const int*)d_in[2];
    const float* W1  = (const float*)d_in[3];
    const float* a1s = (const float*)d_in[4];
    const float* a1d = (const float*)d_in[5];
    const float* b1  = (const float*)d_in[6];
    const float* W2  = (const float*)d_in[7];
    const float* a2s = (const float*)d_in[8];
    const float* a2d = (const float*)d_in[9];
    const float* b2  = (const float*)d_in[10];
    const float* W3  = (const float*)d_in[11];
    const float* a3s = (const float*)d_in[12];
    const float* a3d = (const float*)d_in[13];
    const float* b3  = (const float*)d_in[14];
    const float* fcW = (const float*)d_in[15];
    const float* fcb = (const float*)d_in[16];

    int E = in_sizes[1] / 2;
    int total = E + NN;
    const int* srcs = ei;
    const int* dsts = ei + E;

    // CSR build (graph static across layers)
    init_deg<<<(NN + 255) / 256, 256>>>();
    count_deg<<<(E + 255) / 256, 256>>>(dsts, E);
    scan_deg<<<1, 1024>>>();
    scatter_edges<<<(total + 255) / 256, 256>>>(srcs, dsts, E, total);

    // layer 1: x -> P,  layer 2: P -> Q,  layer 3: Q -> P
    run_layer(x,       0, 1, W1, a1s, a1d, b1);
    run_layer(nullptr, 1, 2, W2, a2s, a2d, b2);
    run_layer(nullptr, 2, 1, W3, a3s, a3d, b3);

    pool_kernel<<<NGRAPH, 256>>>(batch, 1);
    fc_kernel<<<1, NGRAPH * OUTCH>>>(fcW, fcb, (float*)d_out);
}

// round 8
// speedup vs baseline: 3.0323x; 1.0295x over previous
#include <cuda_runtime.h>
#include <cuda_bf16.h>
#include <cuda_fp16.h>
#include <cstdint>

// Problem constants (fixed by the dataset)
#define NN      50000
#define FDIM    128
#define HEADS   4
#define NGRAPH  64
#define OUTCH   10
#define NEG     0.2f
#define MAXE    800000
#define MAXTOT  (MAXE + NN)   // edges + self loops

// ---------------- device scratch (static, no allocation) ----------------
__device__ __align__(16) __half g_Hh[NN * FDIM];   // gemm output (pre-bias h), fp16
__device__ __align__(16) float  g_P[NN * FDIM];    // ping buffer
__device__ __align__(16) float  g_Q[NN * FDIM];    // pong buffer
__device__ __align__(16) float  g_asrc[NN * HEADS];
__device__ __align__(16) float  g_adst[NN * HEADS];
__device__ __align__(16) float  g_ex[MAXTOT * HEADS]; // exp(e) per edge per head
__device__ __align__(16) float  g_pooled[NGRAPH * FDIM];
// W split into fp16 hi/lo, transposed to [n][k] (per layer, pre-GEMM)
__device__ __align__(16) __half g_Wt_hi[FDIM * FDIM];
__device__ __align__(16) __half g_Wt_lo[FDIM * FDIM];
// CSR by destination (built once per launch; graph static across layers)
__device__ int g_deg[NN];
__device__ int g_off[NN + 1];
__device__ int g_cursor[NN];
__device__ int g_csr_src[MAXTOT];

__device__ __forceinline__ float lrelu(float e) { return e > 0.f ? e : NEG * e; }

__device__ __forceinline__ float* sel_buf(int sel) {
    return sel == 1 ? g_P : g_Q;
}
__device__ __forceinline__ const float* sel_x(const float* ext, int sel) {
    return sel == 0 ? ext : (sel == 1 ? g_P : g_Q);
}

// ================= CSR build (once per launch) =================
__global__ void init_deg() {
    int i = blockIdx.x * blockDim.x + threadIdx.x;
    if (i < NN) g_deg[i] = 1;          // self loop
}
__global__ void count_deg(const int* __restrict__ dsts, int E) {
    int i = blockIdx.x * blockDim.x + threadIdx.x;
    if (i < E) atomicAdd(&g_deg[dsts[i]], 1);
}
// one block, 1024 threads: chunked exclusive scan of g_deg -> g_off, g_cursor
__global__ void scan_deg() {
    __shared__ int part[1024];
    const int CH = (NN + 1023) / 1024;   // 49
    int t = threadIdx.x;
    int base = t * CH;
    int s = 0;
    for (int k = 0; k < CH; k++) {
        int idx = base + k;
        if (idx < NN) s += g_deg[idx];
    }
    part[t] = s;
    __syncthreads();
    for (int off = 1; off < 1024; off <<= 1) {
        int v = (t >= off) ? part[t - off] : 0;
        __syncthreads();
        part[t] += v;
        __syncthreads();
    }
    int run = part[t] - s;     // exclusive start of this chunk
    for (int k = 0; k < CH; k++) {
        int idx = base + k;
        if (idx < NN) {
            g_off[idx]    = run;
            g_cursor[idx] = run;
            run += g_deg[idx];
        }
    }
    if (t == 0) g_off[NN] = part[1023];
}
__global__ void scatter_edges(const int* __restrict__ srcs,
                              const int* __restrict__ dsts, int E, int total) {
    int i = blockIdx.x * blockDim.x + threadIdx.x;
    if (i >= total) return;
    int s, d;
    if (i < E) { s = srcs[i]; d = dsts[i]; }
    else       { s = d = i - E; }
    int pos = atomicAdd(&g_cursor[d], 1);
    g_csr_src[pos] = s;
}

// ========== W -> fp16 hi/lo, transposed [n][k] (per layer) ==========
__global__ void conv_w(const float* __restrict__ W) {
    int i = blockIdx.x * blockDim.x + threadIdx.x;
    if (i >= FDIM * FDIM) return;
    int k = i >> 7, n = i & 127;
    float v = W[i];                       // W[k][n]
    __half h = __float2half_rn(v);
    __half l = __float2half_rn(v - __half2float(h));
    g_Wt_hi[n * FDIM + k] = h;
    g_Wt_lo[n * FDIM + k] = l;
}

// ======= GEMM via mma.sync fp16 hi/lo split: H = X(N,128) @ W(128,128) =======
// 128-row tile per block, 256 threads (8 warps x 16 rows). Fused attn epilogue.
#define SA 136                    // smem row stride in halfs (conflict-free)
#define GSM_BYTES (4 * 128 * SA * 2)   // Ahi, Alo, Bhi, Blo = 139264 B

__device__ __forceinline__ void mma16816(float* c, uint32_t a0, uint32_t a1,
                                         uint32_t a2, uint32_t a3,
                                         uint32_t b0, uint32_t b1) {
    asm volatile(
        "mma.sync.aligned.m16n8k16.row.col.f32.f16.f16.f32 "
        "{%0,%1,%2,%3}, {%4,%5,%6,%7}, {%8,%9}, {%0,%1,%2,%3};"
        : "+f"(c[0]), "+f"(c[1]), "+f"(c[2]), "+f"(c[3])
        : "r"(a0), "r"(a1), "r"(a2), "r"(a3), "r"(b0), "r"(b1));
}

__global__ void __launch_bounds__(256) gemm_mma(const float* __restrict__ Xext,
                                                int xsel,
                                                const float* __restrict__ a_s,
                                                const float* __restrict__ a_d) {
    extern __shared__ __align__(16) __half smh[];
    __half* Ahi = smh;
    __half* Alo = Ahi + 128 * SA;
    __half* Bhi = Alo + 128 * SA;
    __half* Blo = Bhi + 128 * SA;
    __shared__ float as_s[128], ad_s[128];

    const float* X = sel_x(Xext, xsel);
    const int tid  = threadIdx.x;
    const int lane = tid & 31;
    const int wid  = tid >> 5;
    const int g    = lane >> 2;       // 0..7
    const int c    = lane & 3;        // 0..3
    const int row0 = blockIdx.x * 128;
    const int arow = wid * 16 + g;    // fragment row within tile

    if (tid < 128) { as_s[tid] = a_s[tid]; ad_s[tid] = a_d[tid]; }

    // ---- fill A tiles (X fp32 -> fp16 hi/lo) ----
    for (int it = tid; it < 128 * 32; it += 256) {
        int r = it >> 5, j = it & 31;          // j: float4 col
        float4 v = make_float4(0.f, 0.f, 0.f, 0.f);
        if (row0 + r < NN)
            v = reinterpret_cast<const float4*>(X)[(row0 + r) * 32 + j];
        __half hx = __float2half_rn(v.x), hy = __float2half_rn(v.y);
        __half hz = __float2half_rn(v.z), hw = __float2half_rn(v.w);
        __half lx = __float2half_rn(v.x - __half2float(hx));
        __half ly = __float2half_rn(v.y - __half2float(hy));
        __half lz = __float2half_rn(v.z - __half2float(hz));
        __half lw = __float2half_rn(v.w - __half2float(hw));
        __half2 h01 = __halves2half2(hx, hy), h23 = __halves2half2(hz, hw);
        __half2 l01 = __halves2half2(lx, ly), l23 = __halves2half2(lz, lw);
        uint2 hv = make_uint2(*(uint32_t*)&h01, *(uint32_t*)&h23);
        uint2 lv = make_uint2(*(uint32_t*)&l01, *(uint32_t*)&l23);
        *reinterpret_cast<uint2*>(&Ahi[r * SA + 4 * j]) = hv;
        *reinterpret_cast<uint2*>(&Alo[r * SA + 4 * j]) = lv;
    }
    // ---- fill B tiles from preconverted g_Wt ([n][k] fp16) ----
    for (int it = tid; it < 128 * 16; it += 256) {
        int n = it >> 4, j = it & 15;          // j: 8-half chunk
        *reinterpret_cast<uint4*>(&Bhi[n * SA + 8 * j]) =
            reinterpret_cast<const uint4*>(g_Wt_hi)[n * 16 + j];
        *reinterpret_cast<uint4*>(&Blo[n * SA + 8 * j]) =
            reinterpret_cast<const uint4*>(g_Wt_lo)[n * 16 + j];
    }
    __syncthreads();

    // ---- mainloop ----
    float acc[16][4];
#pragma unroll
    for (int nt = 0; nt < 16; nt++)
#pragma unroll
        for (int q = 0; q < 4; q++) acc[nt][q] = 0.f;

#pragma unroll
    for (int ks = 0; ks < 8; ks++) {
        const int kb = ks * 16 + 2 * c;
        uint32_t ah0 = *(uint32_t*)&Ahi[arow * SA + kb];
        uint32_t ah1 = *(uint32_t*)&Ahi[(arow + 8) * SA + kb];
        uint32_t ah2 = *(uint32_t*)&Ahi[arow * SA + kb + 8];
        uint32_t ah3 = *(uint32_t*)&Ahi[(arow + 8) * SA + kb + 8];
        uint32_t al0 = *(uint32_t*)&Alo[arow * SA + kb];
        uint32_t al1 = *(uint32_t*)&Alo[(arow + 8) * SA + kb];
        uint32_t al2 = *(uint32_t*)&Alo[arow * SA + kb + 8];
        uint32_t al3 = *(uint32_t*)&Alo[(arow + 8) * SA + kb + 8];
#pragma unroll
        for (int nt = 0; nt < 16; nt++) {
            const int nrow = nt * 8 + g;
            uint32_t bh0 = *(uint32_t*)&Bhi[nrow * SA + kb];
            uint32_t bh1 = *(uint32_t*)&Bhi[nrow * SA + kb + 8];
            uint32_t bl0 = *(uint32_t*)&Blo[nrow * SA + kb];
            uint32_t bl1 = *(uint32_t*)&Blo[nrow * SA + kb + 8];
            mma16816(acc[nt], ah0, ah1, ah2, ah3, bh0, bh1);
            mma16816(acc[nt], ah0, ah1, ah2, ah3, bl0, bl1);
            mma16816(acc[nt], al0, al1, al2, al3, bh0, bh1);
        }
    }

    // ---- epilogue: attn scalars from accumulators + fp16 H store ----
    float ps[2][4], pd[2][4];
#pragma unroll
    for (int r2 = 0; r2 < 2; r2++)
#pragma unroll
        for (int h = 0; h < 4; h++) { ps[r2][h] = 0.f; pd[r2][h] = 0.f; }

#pragma unroll
    for (int nt = 0; nt < 16; nt++) {
        const int head = nt >> 2;
        const int col = nt * 8 + 2 * c;
        float s0 = as_s[col], s1 = as_s[col + 1];
        float d0 = ad_s[col], d1 = ad_s[col + 1];
        ps[0][head] += acc[nt][0] * s0 + acc[nt][1] * s1;
        pd[0][head] += acc[nt][0] * d0 + acc[nt][1] * d1;
        ps[1][head] += acc[nt][2] * s0 + acc[nt][3] * s1;
        pd[1][head] += acc[nt][2] * d0 + acc[nt][3] * d1;
    }
#pragma unroll
    for (int off = 1; off <= 2; off <<= 1)
#pragma unroll
        for (int r2 = 0; r2 < 2; r2++)
#pragma unroll
            for (int h = 0; h < 4; h++) {
                ps[r2][h] += __shfl_xor_sync(0xffffffffu, ps[r2][h], off);
                pd[r2][h] += __shfl_xor_sync(0xffffffffu, pd[r2][h], off);
            }
    if (c == 0) {
        int rA = row0 + arow, rB = rA + 8;
        if (rA < NN) {
            reinterpret_cast<float4*>(g_asrc)[rA] =
                make_float4(ps[0][0], ps[0][1], ps[0][2], ps[0][3]);
            reinterpret_cast<float4*>(g_adst)[rA] =
                make_float4(pd[0][0], pd[0][1], pd[0][2], pd[0][3]);
        }
        if (rB < NN) {
            reinterpret_cast<float4*>(g_asrc)[rB] =
                make_float4(ps[1][0], ps[1][1], ps[1][2], ps[1][3]);
            reinterpret_cast<float4*>(g_adst)[rB] =
                make_float4(pd[1][0], pd[1][1], pd[1][2], pd[1][3]);
        }
    }

    {
        int rA = row0 + arow, rB = rA + 8;
#pragma unroll
        for (int nt = 0; nt < 16; nt++) {
            const int col = nt * 8 + 2 * c;
            if (rA < NN) {
                __half2 v = __floats2half2_rn(acc[nt][0], acc[nt][1]);
                *reinterpret_cast<uint32_t*>(&g_Hh[rA * 128 + col]) =
                    *reinterpret_cast<uint32_t*>(&v);
            }
            if (rB < NN) {
                __half2 v = __floats2half2_rn(acc[nt][2], acc[nt][3]);
                *reinterpret_cast<uint32_t*>(&g_Hh[rB * 128 + col]) =
                    *reinterpret_cast<uint32_t*>(&v);
            }
        }
    }
}

// ======= fused softmax + aggregate: one warp per destination node =======
// No max pass: softmax(e) == softmax(e - m); e is O(+-5) so exp is safe
// (clamped at 30 as a guard). exp(e) cached per edge in g_ex.
__global__ void __launch_bounds__(256) fused_edge(int aggsel,
                                                  const float* __restrict__ b) {
    int gw   = (blockIdx.x * blockDim.x + threadIdx.x) >> 5;
    int lane = threadIdx.x & 31;
    if (gw >= NN) return;
    const int d   = gw;
    const int beg = g_off[d];
    const int end = g_off[d + 1];   // >= beg+1 (self loop)

    float4 ad4 = reinterpret_cast<const float4*>(g_adst)[d];

    // pass 1: exp(e) per edge (cached) + per-head denominator
    float s0 = 0.f, s1 = 0.f, s2 = 0.f, s3 = 0.f;
    for (int i = beg + lane; i < end; i += 32) {
        int s = g_csr_src[i];
        float4 as = reinterpret_cast<const float4*>(g_asrc)[s];
        float x0 = __expf(fminf(lrelu(as.x + ad4.x), 30.f));
        float x1 = __expf(fminf(lrelu(as.y + ad4.y), 30.f));
        float x2 = __expf(fminf(lrelu(as.z + ad4.z), 30.f));
        float x3 = __expf(fminf(lrelu(as.w + ad4.w), 30.f));
        reinterpret_cast<float4*>(g_ex)[i] = make_float4(x0, x1, x2, x3);
        s0 += x0; s1 += x1; s2 += x2; s3 += x3;
    }
#pragma unroll
    for (int off = 16; off > 0; off >>= 1) {
        s0 += __shfl_xor_sync(0xffffffffu, s0, off);
        s1 += __shfl_xor_sync(0xffffffffu, s1, off);
        s2 += __shfl_xor_sync(0xffffffffu, s2, off);
        s3 += __shfl_xor_sync(0xffffffffu, s3, off);
    }
    float r0 = 1.f / (s0 + 1e-16f);
    float r1 = 1.f / (s1 + 1e-16f);
    float r2 = 1.f / (s2 + 1e-16f);
    float r3 = 1.f / (s3 + 1e-16f);

    __threadfence_block();   // make this warp's g_ex stores visible to all lanes
    __syncwarp();

    // lanes 0-3 hold reciprocal denominator for head = lane
    float rl = (lane & 2) ? ((lane & 1) ? r3 : r2) : ((lane & 1) ? r1 : r0);
    const int h = lane >> 3;   // head owning this lane's 4 features

    // pass 2: whole-warp per edge, fp16 h gather, accumulate fp32, single store
    float4 acc = make_float4(0.f, 0.f, 0.f, 0.f);
    for (int i = beg; i < end; i++) {
        int s = g_csr_src[i];                 // broadcast load
        float a = 0.f;
        if (lane < 4)
            a = g_ex[i * 4 + lane] * rl;      // one 16B line, broadcast
        a = __shfl_sync(0xffffffffu, a, h);
        uint2 hv = reinterpret_cast<const uint2*>(g_Hh)[s * 32 + lane]; // 4 halfs
        float2 f01 = __half22float2(*reinterpret_cast<__half2*>(&hv.x));
        float2 f23 = __half22float2(*reinterpret_cast<__half2*>(&hv.y));
        acc.x += a * f01.x;
        acc.y += a * f01.y;
        acc.z += a * f23.x;
        acc.w += a * f23.y;
    }
    float4 bb = reinterpret_cast<const float4*>(b)[lane];
    float4 o;
    o.x = fmaxf(acc.x + bb.x, 0.f);
    o.y = fmaxf(acc.y + bb.y, 0.f);
    o.z = fmaxf(acc.z + bb.z, 0.f);
    o.w = fmaxf(acc.w + bb.w, 0.f);
    reinterpret_cast<float4*>(sel_buf(aggsel))[d * 32 + lane] = o;
}

// ---------------- mean pool per graph (batch is sorted int32) ----------------
__device__ __forceinline__ int lbound_i(const int* a, int n, int v) {
    int lo = 0, hi = n;
    while (lo < hi) {
        int mid = (lo + hi) >> 1;
        if (a[mid] < v) lo = mid + 1; else hi = mid;
    }
    return lo;
}

__global__ void pool_kernel(const int* __restrict__ batch, int sel) {
    __shared__ int se[2];
    __shared__ float s[128];
    int g = blockIdx.x;
    int t = threadIdx.x;
    if (t == 0) {
        se[0] = lbound_i(batch, NN, g);
        se[1] = lbound_i(batch, NN, g + 1);
    }
    __syncthreads();
    int start = se[0], end = se[1];
    const float* h = sel_buf(sel);
    int f = t & 127;
    float acc = 0.f;
    for (int n = start + (t >> 7); n < end; n += 2)
        acc += h[n * 128 + f];
    if (t < 128) s[t] = acc;
    __syncthreads();
    if (t >= 128) s[f] += acc;   // exactly one writer per f
    __syncthreads();
    if (t < 128)
        g_pooled[g * 128 + t] = s[t] / fmaxf((float)(end - start), 1.0f);
}

// ---------------- final FC: [64,128] @ [128,10] + b ----------------
__global__ void fc_kernel(const float* __restrict__ fcW,
                          const float* __restrict__ fcb,
                          float* __restrict__ out) {
    int t = threadIdx.x;
    if (t >= NGRAPH * OUTCH) return;
    int g = t / OUTCH, o = t % OUTCH;
    float acc = fcb[o];
#pragma unroll 8
    for (int k = 0; k < 128; k++)
        acc += g_pooled[g * 128 + k] * fcW[k * OUTCH + o];
    out[t] = acc;
}

// ---------------- driver ----------------
static void run_layer(const float* x_ext, int xsel, int aggsel,
                      const float* W, const float* a_s, const float* a_d,
                      const float* b) {
    conv_w<<<(FDIM * FDIM + 255) / 256, 256>>>(W);
    gemm_mma<<<(NN + 127) / 128, 256, GSM_BYTES>>>(x_ext, xsel, a_s, a_d);
    fused_edge<<<(NN + 7) / 8, 256>>>(aggsel, b);
}

extern "C" void kernel_launch(void* const* d_in, const int* in_sizes, int n_in,
                              void* d_out, int out_size) {
    const float* x     = (const float*)d_in[0];
    const int*   ei    = (const int*)d_in[1];    // int32 (JAX x64 disabled)
    const int*   batch = (const int*)d_in[2];
    const float* W1  = (const float*)d_in[3];
    const float* a1s = (const float*)d_in[4];
    const float* a1d = (const float*)d_in[5];
    const float* b1  = (const float*)d_in[6];
    const float* W2  = (const float*)d_in[7];
    const float* a2s = (const float*)d_in[8];
    const float* a2d = (const float*)d_in[9];
    const float* b2  = (const float*)d_in[10];
    const float* W3  = (const float*)d_in[11];
    const float* a3s = (const float*)d_in[12];
    const float* a3d = (const float*)d_in[13];
    const float* b3  = (const float*)d_in[14];
    const float* fcW = (const float*)d_in[15];
    const float* fcb = (const float*)d_in[16];

    cudaFuncSetAttribute(gemm_mma, cudaFuncAttributeMaxDynamicSharedMemorySize,
                         GSM_BYTES);

    int E = in_sizes[1] / 2;
    int total = E + NN;
    const int* srcs = ei;
    const int* dsts = ei + E;

    // CSR build (graph static across layers)
    init_deg<<<(NN + 255) / 256, 256>>>();
    count_deg<<<(E + 255) / 256, 256>>>(dsts, E);
    scan_deg<<<1, 1024>>>();
    scatter_edges<<<(total + 255) / 256, 256>>>(srcs, dsts, E, total);

    // layer 1: x -> P,  layer 2: P -> Q,  layer 3: Q -> P
    run_layer(x,       0, 1, W1, a1s, a1d, b1);
    run_layer(nullptr, 1, 2, W2, a2s, a2d, b2);
    run_layer(nullptr, 2, 1, W3, a3s, a3d, b3);

    pool_kernel<<<NGRAPH, 256>>>(batch, 1);
    fc_kernel<<<1, NGRAPH * OUTCH>>>(fcW, fcb, (float*)d_out);
}